// round 8
// baseline (speedup 1.0000x reference)
#include <cuda_runtime.h>
#include <math.h>

// ---------------------------------------------------------------------------
// Problem constants
// ---------------------------------------------------------------------------
#define BB      64      // batch
#define FRAMES  100
#define FF      193     // feature rows (last one = period)
#define SS      64
#define LL      512
#define NSUB    4

// Packed transposed-weight offsets (layout (K, O), row k contiguous in o)
#define OFF_FW   0        // (388,64)   24832
#define OFF_FWG  24832    // (64,64)    4096
#define OFF_IH1  28928    // (128,192)  24576
#define OFF_HH1  53504    // (64,192)   12288
#define OFF_IH2  65792
#define OFF_HH2  90368
#define OFF_IH3  102656
#define OFF_HH3  127232
#define OFF_G1   139520   // (64,64)
#define OFF_G2   143616
#define OFF_G3   147712
#define OFF_SG   151808   // (128,128)  16384
#define OFF_SD   168192   // (320,128)  40960
#define OFF_OUT  209152   // (128,64)   8192
#define WT_TOTAL 217344

// ---------------------------------------------------------------------------
// Device scratch (allocation-free: __device__ globals), 16B-aligned for float4
// ---------------------------------------------------------------------------
__device__ __align__(16) float g_X [6400 * 256];
__device__ __align__(16) float g_H1[6400 * 256];
__device__ __align__(16) float g_H2[6400 * 256];
__device__ __align__(16) float g_C [6400 * 512];
__device__ __align__(16) float g_WT[WT_TOTAL];

// ---------------------------------------------------------------------------
// Accurate activations (expm1f is not substituted by fast-math; no
// cancellation in either formulation). Cheap vs the matvec FMA volume.
// ---------------------------------------------------------------------------
__device__ __forceinline__ float tanh_acc(float x) {
    float t  = fabsf(x);
    float em = expm1f(-2.0f * t);        // in (-1, 0]
    float r  = -em / (2.0f + em);        // tanh(t)
    return copysignf(r, x);
}

__device__ __forceinline__ float sig_acc(float x) {
    if (x >= 0.0f) {
        float em = expm1f(-x);
        return 1.0f / (2.0f + em);
    } else {
        float em = expm1f(x);
        return (1.0f + em) / (2.0f + em);
    }
}

// ---------------------------------------------------------------------------
// Block-cooperative matvec:  y[o] = act( sum_k W[k*O + o] * x[k] ),  o < O
// W is (K, O) transposed layout. 256 threads; thread owns 4 outputs and a
// k-residue class; partials reduced through smem. Coalesced float4 loads.
// ---------------------------------------------------------------------------
template<int O, int K, int ACT>
__device__ __forceinline__ void mv(const float* __restrict__ W,
                                   const float* __restrict__ x,
                                   float* __restrict__ y,
                                   float* __restrict__ redf,
                                   int tid)
{
    constexpr int G = O / 4;        // output groups of 4
    constexpr int P = 256 / G;      // k-split factor (16 / 8 / 5)
    const int g = tid % G;
    const int p = tid / G;
    float4 acc = make_float4(0.f, 0.f, 0.f, 0.f);
    if (p < P) {
        #pragma unroll
        for (int k = p; k < K; k += P) {
            float4 w = *reinterpret_cast<const float4*>(W + k * O + 4 * g);
            float xv = x[k];
            acc.x = fmaf(w.x, xv, acc.x);
            acc.y = fmaf(w.y, xv, acc.y);
            acc.z = fmaf(w.z, xv, acc.z);
            acc.w = fmaf(w.w, xv, acc.w);
        }
        *reinterpret_cast<float4*>(redf + p * O + 4 * g) = acc;
    }
    __syncthreads();
    if (tid < O) {
        float s = 0.f;
        #pragma unroll
        for (int q = 0; q < P; ++q) s += redf[q * O + tid];
        y[tid] = ACT ? tanh_acc(s) : s;
    }
    __syncthreads();
}

// GRU + GLU stage. xg = [input(64) | prev_sub(64)], s updated in place to the
// GRU state g; GLU(g) written to skipslot and (for chaining) into xg[0:64].
__device__ __forceinline__ void gru_glu(const float* WihT, const float* WhhT,
                                        const float* WgT,
                                        float* s, float* skipslot, float* xg,
                                        float* gi, float* gh, float* t64,
                                        float* redf, int tid)
{
    mv<192, 128, 0>(WihT, xg, gi, redf, tid);
    mv<192, 64, 0>(WhhT, s, gh, redf, tid);
    if (tid < 64) {
        float r = sig_acc(gi[tid]        + gh[tid]);
        float z = sig_acc(gi[64 + tid]   + gh[64 + tid]);
        float n = tanh_acc(gi[128 + tid] + r * gh[128 + tid]);
        s[tid] = (1.0f - z) * n + z * s[tid];
    }
    __syncthreads();
    mv<64, 64, 0>(WgT, s, t64, redf, tid);
    if (tid < 64) {
        float o = s[tid] * sig_acc(t64[tid]);
        skipslot[tid] = o;
        xg[tid] = o;
    }
    __syncthreads();
}

// ---------------------------------------------------------------------------
// Prep kernels
// ---------------------------------------------------------------------------
__global__ void build_x_kernel(const float* __restrict__ features,
                               const float* __restrict__ gfeat)
{
    int r = blockIdx.x;            // r = b*FRAMES + t
    int tid = threadIdx.x;
    int b = r / FRAMES, t = r % FRAMES;
    float v;
    if (tid < 192) v = features[b * (FF * FRAMES) + tid * FRAMES + t];
    else           v = gfeat[b * 64 + (tid - 192)];
    g_X[r * 256 + tid] = v;
}

// One fused transpose kernel for all 14 weight matrices.
struct TPack { const float* src[14]; };

__global__ void transpose_all_kernel(TPack p)
{
    const int offs[14] = {OFF_FW, OFF_FWG, OFF_IH1, OFF_HH1, OFF_IH2, OFF_HH2,
                          OFF_IH3, OFF_HH3, OFF_G1, OFF_G2, OFF_G3, OFF_SG,
                          OFF_SD, OFF_OUT};
    const int Os[14]   = {64, 64, 192, 192, 192, 192, 192, 192,
                          64, 64, 64, 128, 128, 64};
    const int Ks[14]   = {388, 64, 128, 64, 128, 64, 128, 64,
                          64, 64, 64, 128, 320, 128};
    int m = blockIdx.y;
    int i = blockIdx.x * 256 + threadIdx.x;
    int O = Os[m], K = Ks[m];
    if (i < O * K) {
        int o = i / K, kk = i % K;
        g_WT[offs[m] + kk * O + o] = p.src[m][i];
    }
}

// Tiled GEMM with fused tanh: C[r,o] = tanh(sum_k A[r,k] * W[o,k]); K = 256.
// mode 0: g_X->g_H1 (O=256); 1: g_H1->g_H2 (O=256); 2: g_H2->g_C (O=512)
__global__ void __launch_bounds__(256) gemm_tanh_kernel(
    const float* __restrict__ W, int mode)
{
    const float* A = (mode == 0) ? g_X : (mode == 1) ? g_H1 : g_H2;
    float* Cm      = (mode == 0) ? g_H1 : (mode == 1) ? g_H2 : g_C;
    const int K = 256;
    const int O = (mode == 2) ? 512 : 256;

    __shared__ __align__(16) float As[16][65];
    __shared__ __align__(16) float Ws[16][65];
    int tid = threadIdx.x;
    int tx = tid & 15, ty = tid >> 4;
    int r0 = blockIdx.x * 64, n0 = blockIdx.y * 64;
    int lm = tid >> 2, lk = (tid & 3) << 2;

    float acc[4][4];
    #pragma unroll
    for (int i = 0; i < 4; ++i)
        #pragma unroll
        for (int j = 0; j < 4; ++j) acc[i][j] = 0.f;

    for (int kk = 0; kk < K; kk += 16) {
        float4 a4 = *reinterpret_cast<const float4*>(A + (size_t)(r0 + lm) * K + kk + lk);
        float4 w4 = *reinterpret_cast<const float4*>(W + (size_t)(n0 + lm) * K + kk + lk);
        As[lk + 0][lm] = a4.x; As[lk + 1][lm] = a4.y;
        As[lk + 2][lm] = a4.z; As[lk + 3][lm] = a4.w;
        Ws[lk + 0][lm] = w4.x; Ws[lk + 1][lm] = w4.y;
        Ws[lk + 2][lm] = w4.z; Ws[lk + 3][lm] = w4.w;
        __syncthreads();
        #pragma unroll
        for (int kq = 0; kq < 16; ++kq) {
            float av[4], wv[4];
            #pragma unroll
            for (int i = 0; i < 4; ++i) av[i] = As[kq][ty * 4 + i];
            #pragma unroll
            for (int j = 0; j < 4; ++j) wv[j] = Ws[kq][tx * 4 + j];
            #pragma unroll
            for (int i = 0; i < 4; ++i)
                #pragma unroll
                for (int j = 0; j < 4; ++j)
                    acc[i][j] = fmaf(av[i], wv[j], acc[i][j]);
        }
        __syncthreads();
    }
    #pragma unroll
    for (int i = 0; i < 4; ++i)
        #pragma unroll
        for (int j = 0; j < 4; ++j)
            Cm[(size_t)(r0 + ty * 4 + i) * O + n0 + tx * 4 + j] = tanh_acc(acc[i][j]);
}

// ---------------------------------------------------------------------------
// Persistent sequential sampler: one CTA per batch element, 400 serial steps.
// prev-sample history lives in a 512-entry smem ring buffer:
//   prev[i] == ring[(head + i) & 511]
// ---------------------------------------------------------------------------
__global__ void __launch_bounds__(256, 1) seq_kernel(
    const float* __restrict__ features,
    const float* __restrict__ prev0,
    float* __restrict__ outg)
{
    extern __shared__ __align__(16) float dynsh[];
    float* WsdS  = dynsh;               // 320*128 = 40960 floats (160 KB)
    float* WoutS = dynsh + 40960;       // 128*64  =  8192 floats ( 32 KB)

    __shared__ __align__(16) float ring[512];
    __shared__ __align__(16) float s1[64], s2[64], s3[64], sfw[128];
    __shared__ __align__(16) float xbuf[388];
    __shared__ __align__(16) float fwpre[64], t64[64], xg[128];
    __shared__ __align__(16) float gi[192], gh[192];
    __shared__ __align__(16) float skipb[320], sd[128], t128[128], so[128], outv[64];
    __shared__ __align__(16) float redf[1024];

    const int tid = threadIdx.x;
    const int b = blockIdx.x;

    for (int i = tid; i < 40960; i += 256) WsdS[i]  = g_WT[OFF_SD + i];
    for (int i = tid; i < 8192;  i += 256) WoutS[i] = g_WT[OFF_OUT + i];
    for (int i = tid; i < 512;   i += 256) ring[i]  = prev0[b * 512 + i];
    if (tid < 64)  { s1[tid] = 0.f; s2[tid] = 0.f; s3[tid] = 0.f; }
    if (tid < 128) sfw[tid] = 0.f;
    __syncthreads();

    int head = 0;
    for (int t = 0; t < FRAMES; ++t) {
        const int per = (int)rintf(features[b * (FF * FRAMES) + (FF - 1) * FRAMES + t]);
        const float* crow = g_C + (b * FRAMES + t) * 512;
        for (int k = 0; k < NSUB; ++k) {
            // -- build xbuf = [feat2s(128) | prev_sub(64) | lookback(68) | sfw(128)]
            if (tid < 128) {
                xbuf[tid]       = crow[tid * 4 + k];
                xbuf[260 + tid] = sfw[tid];
            } else if (tid < 192) {
                int i = tid - 128;
                xbuf[tid] = ring[(head + 448 + i) & 511];
            }
            // Lookback: 68 entries (j = 0..67) handled by threads 188..255.
            // (Previous rounds' bug: `tid < 260` writer only covered j < 64,
            //  leaving xbuf[256..260) stale every step -> 1.9e-2 rel_err.)
            if (tid >= 188) {
                int j = tid - 188;                  // 0..67
                int idx = 512 - per + j - 2;
                if (idx >= 512) idx -= per;
                xbuf[192 + j] = ring[(head + idx) & 511];
            }
            if (tid >= 64 && tid < 128)   // skipb[256:320] = prev_sub
                skipb[192 + tid] = ring[(head + 448 + (tid - 64)) & 511];
            __syncthreads();

            // -- fw = glu(tanh(xbuf @ Wfw^T), Wfw_g)
            mv<64, 388, 1>(g_WT + OFF_FW, xbuf, fwpre, redf, tid);
            mv<64, 64, 0>(g_WT + OFF_FWG, fwpre, t64, redf, tid);
            if (tid < 64) {
                float v = fwpre[tid] * sig_acc(t64[tid]);
                skipb[192 + tid] = v;   // skip slot: fw
                xg[tid] = v;            // GRU1 input
            }
            if (tid >= 64 && tid < 128) xg[tid] = skipb[192 + tid]; // prev_sub
            __syncthreads();

            // -- 3 x (GRU + GLU)
            gru_glu(g_WT + OFF_IH1, g_WT + OFF_HH1, g_WT + OFF_G1,
                    s1, skipb + 0,   xg, gi, gh, t64, redf, tid);
            gru_glu(g_WT + OFF_IH2, g_WT + OFF_HH2, g_WT + OFF_G2,
                    s2, skipb + 64,  xg, gi, gh, t64, redf, tid);
            gru_glu(g_WT + OFF_IH3, g_WT + OFF_HH3, g_WT + OFF_G3,
                    s3, skipb + 128, xg, gi, gh, t64, redf, tid);

            // -- skip decoder + output
            mv<128, 320, 1>(WsdS, skipb, sd, redf, tid);
            mv<128, 128, 0>(g_WT + OFF_SG, sd, t128, redf, tid);
            if (tid < 128) so[tid] = sd[tid] * sig_acc(t128[tid]);
            __syncthreads();
            mv<64, 128, 1>(WoutS, so, outv, redf, tid);

            // -- emit, roll ring, update sfw state
            if (tid < 64) {
                float v = outv[tid];
                outg[b * 25600 + t * 256 + k * 64 + tid] = v;
                ring[(head + tid) & 511] = v;   // overwrites oldest 64
            }
            if (tid < 128) sfw[tid] = xbuf[tid];  // new sfw = current feat2s
            __syncthreads();
            head = (head + 64) & 511;
        }
    }
}

// ---------------------------------------------------------------------------
// Host launcher (graph-capturable: kernel launches only)
// ---------------------------------------------------------------------------
extern "C" void kernel_launch(void* const* d_in, const int* in_sizes, int n_in,
                              void* d_out, int out_size)
{
    const float* features = (const float*)d_in[0];
    const float* gfeat    = (const float*)d_in[1];
    const float* prev     = (const float*)d_in[2];
    const float* Wc1      = (const float*)d_in[3];
    const float* Wc2      = (const float*)d_in[4];
    const float* Wc3      = (const float*)d_in[5];
    float* out = (float*)d_out;

    build_x_kernel<<<6400, 256>>>(features, gfeat);

    TPack tp;
    for (int i = 0; i < 14; ++i) tp.src[i] = (const float*)d_in[6 + i];
    transpose_all_kernel<<<dim3(160, 14), 256>>>(tp);

    gemm_tanh_kernel<<<dim3(100, 4), 256>>>(Wc1, 0);
    gemm_tanh_kernel<<<dim3(100, 4), 256>>>(Wc2, 1);
    gemm_tanh_kernel<<<dim3(100, 8), 256>>>(Wc3, 2);

    cudaFuncSetAttribute(seq_kernel,
                         cudaFuncAttributeMaxDynamicSharedMemorySize, 196608);
    seq_kernel<<<BB, 256, 196608>>>(features, prev, out);
}